// round 11
// baseline (speedup 1.0000x reference)
#include <cuda_runtime.h>
#include <cstddef>

// PCEN: out = (x / (FLOOR + ema(x))^alpha + delta)^(1/root) - delta^(1/root)
// ema: m_t = s*x_t + (1-s)*m_{t-1}, m_0 = x_0, s = 0.025.
//
// R11: full-row warps. Each thread handles 4 channels (LDG.128/STG.128), so
// ONE warp covers the whole 512 B channel row and a 16-row tile is a single
// sequential 8 KB read burst + 8 KB write burst -> maximal DRAM page
// locality, 4x fewer LSU ops. 512 warps (1 per (b,chunk)), 4 independent
// EMA chains per thread (ILP-4 hides single-warp issue latency).
// NC=8, CHUNK=512, HALO=256, static double buffer, stcs, launch_bounds(32,1).

namespace {
constexpr int   Bn = 64, Tn = 4096, Cn = 128;
constexpr float S_COEF = 0.025f;
constexpr float INV_S  = 40.0f;           // 1/s
constexpr float OMS    = 0.975f;
constexpr float FLOORV = 1e-6f;
constexpr int   NC     = 8;               // chunks along T
constexpr int   CHUNK  = Tn / NC;         // 512
constexpr int   HALO   = 256;             // burn-in rows (decay ~1.5e-3)
constexpr int   U      = 16;              // rows per tile (8 KB burst)
constexpr int   THREADS = 32;             // 1 warp/block
constexpr int   NWARPS  = Bn * NC;        // 512 warps
constexpr int   NBLOCKS = NWARPS;         // 512 blocks
static_assert(CHUNK % U == 0 && HALO % U == 0, "tiles must divide regions");
static_assert((CHUNK / U) % 2 == 0 && ((CHUNK + HALO) / U) % 2 == 0,
              "double-buffer loop needs even tile count");
}

__device__ __forceinline__ float f_lg2(float x) {
    float r; asm("lg2.approx.f32 %0, %1;" : "=f"(r) : "f"(x)); return r;
}
__device__ __forceinline__ float f_ex2(float x) {
    float r; asm("ex2.approx.f32 %0, %1;" : "=f"(r) : "f"(x)); return r;
}
__device__ __forceinline__ float f_sqt(float x) {
    float r; asm("sqrt.approx.f32 %0, %1;" : "=f"(r) : "f"(x)); return r;
}

// Pointwise PCEN. mp = m/S (scaled EMA state). SQ = (1/root == 0.5) fast path.
template <bool SQ>
__device__ __forceinline__ float pcen_pt(float xv, float mp, float na, float d,
                                         float ri, float t3) {
    float mm     = fmaf(S_COEF, mp, FLOORV);       // FLOOR + m (off the chain)
    float inv_t1 = f_ex2(na * f_lg2(mm));          // (FLOOR+m)^(-alpha)
    float y      = fmaf(xv, inv_t1, d);            // x/term1 + delta
    float t2     = SQ ? f_sqt(y) : f_ex2(ri * f_lg2(y));
    return t2 - t3;
}

// Consume one U-row float4 tile held in registers. emit is warp-uniform.
template <bool SQ>
__device__ __forceinline__ void consume_tile(const float4* __restrict__ xs,
                                             bool emit, float4* __restrict__ po,
                                             int emit_off, float4& m,
                                             float4 na, float4 d, float4 ri,
                                             float4 t3) {
    if (emit) {
        float4* pot = po + (size_t)emit_off * 32;
        #pragma unroll
        for (int i = 0; i < U; ++i) {
            m.x = fmaf(OMS, m.x, xs[i].x);         // 4 independent chains (ILP-4)
            m.y = fmaf(OMS, m.y, xs[i].y);
            m.z = fmaf(OMS, m.z, xs[i].z);
            m.w = fmaf(OMS, m.w, xs[i].w);
            float4 o;
            o.x = pcen_pt<SQ>(xs[i].x, m.x, na.x, d.x, ri.x, t3.x);
            o.y = pcen_pt<SQ>(xs[i].y, m.y, na.y, d.y, ri.y, t3.y);
            o.z = pcen_pt<SQ>(xs[i].z, m.z, na.z, d.z, ri.z, t3.z);
            o.w = pcen_pt<SQ>(xs[i].w, m.w, na.w, d.w, ri.w, t3.w);
            __stcs(pot + i * 32, o);
        }
    } else {
        #pragma unroll
        for (int i = 0; i < U; ++i) {
            m.x = fmaf(OMS, m.x, xs[i].x);
            m.y = fmaf(OMS, m.y, xs[i].y);
            m.z = fmaf(OMS, m.z, xs[i].z);
            m.w = fmaf(OMS, m.w, xs[i].w);
        }
    }
}

template <bool SQ>
__device__ __forceinline__ void run_seq(const float4* __restrict__ p,
                                        float4* __restrict__ po,
                                        int NH, int NT,
                                        float4 na, float4 d, float4 ri, float4 t3) {
    // scaled EMA state m' = m/S. Init m' = 40*x0 so consuming row 0 of tile 0
    // yields m = x[tstart] (exact for chunk 0 through the normal emit path).
    float4 x0 = p[0];
    float4 m;
    m.x = INV_S * x0.x;  m.y = INV_S * x0.y;
    m.z = INV_S * x0.z;  m.w = INV_S * x0.w;

    float4 bufA[U], bufB[U];
    #pragma unroll
    for (int i = 0; i < U; ++i) bufA[i] = p[i * 32];        // preload tile 0

    // NT is even (32 or 48): tile t+1 always exists inside the loop.
    for (int t = 0; t < NT; t += 2) {
        const float4* p1 = p + (size_t)(t + 1) * U * 32;
        #pragma unroll
        for (int i = 0; i < U; ++i) bufB[i] = p1[i * 32];   // prefetch t+1

        consume_tile<SQ>(bufA, t >= NH, po, (t - NH) * U, m, na, d, ri, t3);

        if (t + 2 < NT) {
            const float4* p2 = p + (size_t)(t + 2) * U * 32;
            #pragma unroll
            for (int i = 0; i < U; ++i) bufA[i] = p2[i * 32];  // prefetch t+2
        }

        consume_tile<SQ>(bufB, t + 1 >= NH, po, (t + 1 - NH) * U, m, na, d, ri, t3);
    }
}

__global__ void __launch_bounds__(THREADS, 1)
pcen_kernel(const float* __restrict__ x,
            const float* __restrict__ alpha,
            const float* __restrict__ delta,
            const float* __restrict__ root,
            float* __restrict__ out) {
    int w    = blockIdx.x;                 // one warp per block
    int lane = threadIdx.x;                // 0..31

    // warp -> (b, chunk); thread -> channels 4*lane..4*lane+3
    int b     = w >> 3;
    int chunk = w & 7;
    int c     = lane * 4;

    // per-channel constants (x4)
    float4 a4 = *(const float4*)(alpha + c);
    float4 d4 = *(const float4*)(delta + c);
    float4 r4 = *(const float4*)(root  + c);

    float4 na, ri, t3;
    na.x = -fminf(a4.x, 1.0f);  na.y = -fminf(a4.y, 1.0f);
    na.z = -fminf(a4.z, 1.0f);  na.w = -fminf(a4.w, 1.0f);
    ri.x = 1.0f / fmaxf(r4.x, 1.0f);  ri.y = 1.0f / fmaxf(r4.y, 1.0f);
    ri.z = 1.0f / fmaxf(r4.z, 1.0f);  ri.w = 1.0f / fmaxf(r4.w, 1.0f);
    bool sq = (ri.x == 0.5f) && (ri.y == 0.5f) && (ri.z == 0.5f) && (ri.w == 0.5f);
    // term3 via the SAME approx path as term2 so the x->0 limit cancels exactly
    t3.x = sq ? f_sqt(d4.x) : f_ex2(ri.x * f_lg2(d4.x));
    t3.y = sq ? f_sqt(d4.y) : f_ex2(ri.y * f_lg2(d4.y));
    t3.z = sq ? f_sqt(d4.z) : f_ex2(ri.z * f_lg2(d4.z));
    t3.w = sq ? f_sqt(d4.w) : f_ex2(ri.w * f_lg2(d4.w));

    int t0     = chunk * CHUNK;
    int tstart = (chunk == 0) ? 0 : (t0 - HALO);
    int NH     = (t0 - tstart) / U;          // 0 (chunk 0) or 16
    int NT     = NH + CHUNK / U;             // 32 or 48 (always even)

    const float4* px = (const float4*)(x   + ((size_t)b * Tn + tstart) * Cn + c);
    float4*       po = (float4*)      (out + ((size_t)b * Tn + t0)     * Cn + c);

    if (sq) run_seq<true >(px, po, NH, NT, na, d4, ri, t3);
    else    run_seq<false>(px, po, NH, NT, na, d4, ri, t3);
}

extern "C" void kernel_launch(void* const* d_in, const int* in_sizes, int n_in,
                              void* d_out, int out_size) {
    const float* x     = (const float*)d_in[0];
    const float* alpha = (const float*)d_in[1];
    const float* delta = (const float*)d_in[2];
    const float* root  = (const float*)d_in[3];
    float*       out   = (float*)d_out;
    (void)in_sizes; (void)n_in; (void)out_size;

    pcen_kernel<<<NBLOCKS, THREADS>>>(x, alpha, delta, root, out);
}

// round 12
// speedup vs baseline: 1.3794x; 1.3794x over previous
#include <cuda_runtime.h>
#include <cstddef>

// PCEN: out = (x / (FLOOR + ema(x))^alpha + delta)^(1/root) - delta^(1/root)
// ema: m_t = s*x_t + (1-s)*m_{t-1}, m_0 = x_0, s = 0.025.
//
// R12: float2 lanes (LDG.64, best measured achieved-BW family) + NC=8
// (compulsory-only DRAM traffic) + U=32 coarse bursts (R10's win).
// 1024 warps, 2 per (b,chunk); static double-buffered pipeline; stcs;
// launch_bounds(64,1) to protect the register budget / MLP.

namespace {
constexpr int   Bn = 64, Tn = 4096, Cn = 128;
constexpr float S_COEF = 0.025f;
constexpr float INV_S  = 40.0f;           // 1/s
constexpr float OMS    = 0.975f;
constexpr float FLOORV = 1e-6f;
constexpr int   NC     = 8;               // chunks along T
constexpr int   CHUNK  = Tn / NC;         // 512
constexpr int   HALO   = 256;             // burn-in rows (decay ~1.5e-3)
constexpr int   U      = 32;              // rows per tile (8 KB/warp in flight)
constexpr int   THREADS = 64;             // 2 warps/block
constexpr int   NWARPS  = Bn * NC * 2;    // 1024 float2-warps
constexpr int   NBLOCKS = NWARPS * 32 / THREADS;  // 512
constexpr int   STRIDE  = Cn / 2;         // float2 elems per T-row
static_assert(CHUNK % U == 0 && HALO % U == 0, "tiles must divide regions");
static_assert((CHUNK / U) % 2 == 0 && ((CHUNK + HALO) / U) % 2 == 0,
              "double-buffer loop needs even tile count");
}

__device__ __forceinline__ float f_lg2(float x) {
    float r; asm("lg2.approx.f32 %0, %1;" : "=f"(r) : "f"(x)); return r;
}
__device__ __forceinline__ float f_ex2(float x) {
    float r; asm("ex2.approx.f32 %0, %1;" : "=f"(r) : "f"(x)); return r;
}
__device__ __forceinline__ float f_sqt(float x) {
    float r; asm("sqrt.approx.f32 %0, %1;" : "=f"(r) : "f"(x)); return r;
}

// Pointwise PCEN. mp = m/S (scaled EMA state). SQ = (1/root == 0.5) fast path.
template <bool SQ>
__device__ __forceinline__ float pcen_pt(float xv, float mp, float na, float d,
                                         float ri, float t3) {
    float mm     = fmaf(S_COEF, mp, FLOORV);       // FLOOR + m (off the chain)
    float inv_t1 = f_ex2(na * f_lg2(mm));          // (FLOOR+m)^(-alpha)
    float y      = fmaf(xv, inv_t1, d);            // x/term1 + delta
    float t2     = SQ ? f_sqt(y) : f_ex2(ri * f_lg2(y));
    return t2 - t3;
}

// Consume one U-row float2 tile held in registers. emit is warp-uniform.
template <bool SQ>
__device__ __forceinline__ void consume_tile(const float2* __restrict__ xs,
                                             bool emit, float2* __restrict__ po,
                                             int emit_off, float& mx, float& my,
                                             float2 na, float2 d, float2 ri,
                                             float2 t3) {
    if (emit) {
        float2* pot = po + (size_t)emit_off * STRIDE;
        #pragma unroll
        for (int i = 0; i < U; ++i) {
            mx = fmaf(OMS, mx, xs[i].x);           // 2 independent chains
            my = fmaf(OMS, my, xs[i].y);
            float2 o;
            o.x = pcen_pt<SQ>(xs[i].x, mx, na.x, d.x, ri.x, t3.x);
            o.y = pcen_pt<SQ>(xs[i].y, my, na.y, d.y, ri.y, t3.y);
            __stcs(pot + i * STRIDE, o);
        }
    } else {
        #pragma unroll
        for (int i = 0; i < U; ++i) {
            mx = fmaf(OMS, mx, xs[i].x);
            my = fmaf(OMS, my, xs[i].y);
        }
    }
}

template <bool SQ>
__device__ __forceinline__ void run_seq(const float2* __restrict__ p,
                                        float2* __restrict__ po,
                                        int NH, int NT,
                                        float2 na, float2 d, float2 ri, float2 t3) {
    // scaled EMA state m' = m/S. Init m' = 40*x0 so consuming row 0 of tile 0
    // yields m = x[tstart] (exact for chunk 0 through the normal emit path).
    float2 x0 = p[0];
    float mx = INV_S * x0.x;
    float my = INV_S * x0.y;

    float2 bufA[U], bufB[U];
    #pragma unroll
    for (int i = 0; i < U; ++i) bufA[i] = p[i * STRIDE];    // preload tile 0

    // NT is even (16 or 24): tile t+1 always exists inside the loop.
    for (int t = 0; t < NT; t += 2) {
        const float2* p1 = p + (size_t)(t + 1) * U * STRIDE;
        #pragma unroll
        for (int i = 0; i < U; ++i) bufB[i] = p1[i * STRIDE];   // prefetch t+1

        consume_tile<SQ>(bufA, t >= NH, po, (t - NH) * U, mx, my, na, d, ri, t3);

        if (t + 2 < NT) {
            const float2* p2 = p + (size_t)(t + 2) * U * STRIDE;
            #pragma unroll
            for (int i = 0; i < U; ++i) bufA[i] = p2[i * STRIDE];  // prefetch t+2
        }

        consume_tile<SQ>(bufB, t + 1 >= NH, po, (t + 1 - NH) * U, mx, my, na, d, ri, t3);
    }
}

__global__ void __launch_bounds__(THREADS, 1)
pcen_kernel(const float* __restrict__ x,
            const float* __restrict__ alpha,
            const float* __restrict__ delta,
            const float* __restrict__ root,
            float* __restrict__ out) {
    int gtid = blockIdx.x * blockDim.x + threadIdx.x;
    int w    = gtid >> 5;
    int lane = threadIdx.x & 31;

    // warp -> (b, chunk, half); 16 warps per batch; thread -> 2 channels
    int b     = w >> 4;
    int r     = w & 15;
    int chunk = r >> 1;
    int half  = r & 1;
    int c     = half * 64 + lane * 2;

    // per-channel constants (x2)
    float2 a2 = *(const float2*)(alpha + c);
    float2 d2 = *(const float2*)(delta + c);
    float2 r2 = *(const float2*)(root  + c);

    float2 na, ri, t3;
    na.x = -fminf(a2.x, 1.0f);
    na.y = -fminf(a2.y, 1.0f);
    ri.x = 1.0f / fmaxf(r2.x, 1.0f);
    ri.y = 1.0f / fmaxf(r2.y, 1.0f);
    bool sq = (ri.x == 0.5f) && (ri.y == 0.5f);
    // term3 via the SAME approx path as term2 so the x->0 limit cancels exactly
    t3.x = sq ? f_sqt(d2.x) : f_ex2(ri.x * f_lg2(d2.x));
    t3.y = sq ? f_sqt(d2.y) : f_ex2(ri.y * f_lg2(d2.y));

    int t0     = chunk * CHUNK;
    int tstart = (chunk == 0) ? 0 : (t0 - HALO);
    int NH     = (t0 - tstart) / U;          // 0 (chunk 0) or 8
    int NT     = NH + CHUNK / U;             // 16 or 24 (always even)

    const float2* px = (const float2*)(x   + ((size_t)b * Tn + tstart) * Cn + c);
    float2*       po = (float2*)      (out + ((size_t)b * Tn + t0)     * Cn + c);

    if (sq) run_seq<true >(px, po, NH, NT, na, d2, ri, t3);
    else    run_seq<false>(px, po, NH, NT, na, d2, ri, t3);
}

extern "C" void kernel_launch(void* const* d_in, const int* in_sizes, int n_in,
                              void* d_out, int out_size) {
    const float* x     = (const float*)d_in[0];
    const float* alpha = (const float*)d_in[1];
    const float* delta = (const float*)d_in[2];
    const float* root  = (const float*)d_in[3];
    float*       out   = (float*)d_out;
    (void)in_sizes; (void)n_in; (void)out_size;

    pcen_kernel<<<NBLOCKS, THREADS>>>(x, alpha, delta, root, out);
}

// round 13
// speedup vs baseline: 1.4007x; 1.0154x over previous
#include <cuda_runtime.h>
#include <cstddef>

// PCEN: out = (x / (FLOOR + ema(x))^alpha + delta)^(1/root) - delta^(1/root)
// ema: m_t = s*x_t + (1-s)*m_{t-1}, m_0 = x_0, s = 0.025.
//
// R13: R10 (float1, U=32 tiles, NC=8, HALO=256, static double buffer, stcs)
// with the 4 quarter-warps of each (b,chunk) CO-LOCATED in one 128-thread
// block and kept in lockstep by a per-tile __syncthreads(). DRAM then sees
// complete 512B rows / 2KB pages arrive together (reads AND writes) instead
// of 4 desynchronized quarter-streams -> fewer page re-activations.

namespace {
constexpr int   Bn = 64, Tn = 4096, Cn = 128;
constexpr float S_COEF = 0.025f;
constexpr float INV_S  = 40.0f;           // 1/s
constexpr float OMS    = 0.975f;
constexpr float FLOORV = 1e-6f;
constexpr int   NC     = 8;               // chunks along T
constexpr int   CHUNK  = Tn / NC;         // 512
constexpr int   HALO   = 256;             // burn-in rows (decay ~1.5e-3)
constexpr int   U      = 32;              // rows per tile
constexpr int   THREADS = 128;            // 4 warps = 4 quarters of one row
constexpr int   NBLOCKS = Bn * NC;        // 512 blocks, one per (b,chunk)
static_assert(CHUNK % U == 0 && HALO % U == 0, "tiles must divide regions");
static_assert((CHUNK / U) % 2 == 0 && ((CHUNK + HALO) / U) % 2 == 0,
              "double-buffer loop needs even tile count");
}

__device__ __forceinline__ float f_lg2(float x) {
    float r; asm("lg2.approx.f32 %0, %1;" : "=f"(r) : "f"(x)); return r;
}
__device__ __forceinline__ float f_ex2(float x) {
    float r; asm("ex2.approx.f32 %0, %1;" : "=f"(r) : "f"(x)); return r;
}
__device__ __forceinline__ float f_sqt(float x) {
    float r; asm("sqrt.approx.f32 %0, %1;" : "=f"(r) : "f"(x)); return r;
}

// Pointwise PCEN. mp = m/S (scaled EMA state). SQ = (1/root == 0.5) fast path.
template <bool SQ>
__device__ __forceinline__ float pcen_pt(float xv, float mp, float na, float d,
                                         float ri, float t3) {
    float mm     = fmaf(S_COEF, mp, FLOORV);       // FLOOR + m (off the chain)
    float inv_t1 = f_ex2(na * f_lg2(mm));          // (FLOOR+m)^(-alpha)
    float y      = fmaf(xv, inv_t1, d);            // x/term1 + delta
    float t2     = SQ ? f_sqt(y) : f_ex2(ri * f_lg2(y));
    return t2 - t3;
}

// Consume one U-row tile held in registers. emit is block-uniform.
template <bool SQ>
__device__ __forceinline__ void consume_tile(const float* __restrict__ xs,
                                             bool emit, float* __restrict__ po,
                                             int emit_off, float& m,
                                             float na, float d, float ri,
                                             float t3) {
    if (emit) {
        float* pot = po + (size_t)emit_off * Cn;
        #pragma unroll
        for (int i = 0; i < U; ++i) {
            m = fmaf(OMS, m, xs[i]);               // 4-cyc dependent chain
            __stcs(pot + i * Cn, pcen_pt<SQ>(xs[i], m, na, d, ri, t3));
        }
    } else {
        #pragma unroll
        for (int i = 0; i < U; ++i) m = fmaf(OMS, m, xs[i]);
    }
}

template <bool SQ>
__device__ __forceinline__ void run_seq(const float* __restrict__ p,
                                        float* __restrict__ po,
                                        int NH, int NT,
                                        float na, float d, float ri, float t3) {
    // scaled EMA state m' = m/S. Init m' = 40*x0 so consuming row 0 of tile 0
    // yields m = x[tstart] (exact for chunk 0 through the normal emit path).
    float m = INV_S * p[0];

    float bufA[U], bufB[U];
    #pragma unroll
    for (int i = 0; i < U; ++i) bufA[i] = p[i * Cn];        // preload tile 0

    // NT is even (16 or 24): tile t+1 always exists inside the loop.
    for (int t = 0; t < NT; t += 2) {
        const float* p1 = p + (size_t)(t + 1) * U * Cn;
        #pragma unroll
        for (int i = 0; i < U; ++i) bufB[i] = p1[i * Cn];   // prefetch t+1

        consume_tile<SQ>(bufA, t >= NH, po, (t - NH) * U, m, na, d, ri, t3);
        __syncthreads();                     // keep 4 quarter-warps in lockstep

        if (t + 2 < NT) {
            const float* p2 = p + (size_t)(t + 2) * U * Cn;
            #pragma unroll
            for (int i = 0; i < U; ++i) bufA[i] = p2[i * Cn];  // prefetch t+2
        }

        consume_tile<SQ>(bufB, t + 1 >= NH, po, (t + 1 - NH) * U, m, na, d, ri, t3);
        __syncthreads();
    }
}

__global__ void __launch_bounds__(THREADS, 1)
pcen_kernel(const float* __restrict__ x,
            const float* __restrict__ alpha,
            const float* __restrict__ delta,
            const float* __restrict__ root,
            float* __restrict__ out) {
    // block -> (b, chunk); thread -> channel
    int b     = blockIdx.x >> 3;
    int chunk = blockIdx.x & 7;
    int c     = threadIdx.x;              // 128 threads = 128 channels

    // per-channel constants
    float a  = fminf(alpha[c], 1.0f);
    float d  = delta[c];
    float ri = 1.0f / fmaxf(root[c], 1.0f);
    float na = -a;
    // block-uniform SQ decision (barriers live inside the branch)
    int sq = __syncthreads_and((ri == 0.5f) ? 1 : 0);
    // term3 via the SAME approx path as term2 so the x->0 limit cancels exactly
    float t3 = sq ? f_sqt(d) : f_ex2(ri * f_lg2(d));

    int t0     = chunk * CHUNK;
    int tstart = (chunk == 0) ? 0 : (t0 - HALO);
    int NH     = (t0 - tstart) / U;          // 0 (chunk 0) or 8
    int NT     = NH + CHUNK / U;             // 16 or 24 (always even)

    const float* px = x   + ((size_t)b * Tn + tstart) * Cn + c;
    float*       po = out + ((size_t)b * Tn + t0)     * Cn + c;

    if (sq) run_seq<true >(px, po, NH, NT, na, d, ri, t3);
    else    run_seq<false>(px, po, NH, NT, na, d, ri, t3);
}

extern "C" void kernel_launch(void* const* d_in, const int* in_sizes, int n_in,
                              void* d_out, int out_size) {
    const float* x     = (const float*)d_in[0];
    const float* alpha = (const float*)d_in[1];
    const float* delta = (const float*)d_in[2];
    const float* root  = (const float*)d_in[3];
    float*       out   = (float*)d_out;
    (void)in_sizes; (void)n_in; (void)out_size;

    pcen_kernel<<<NBLOCKS, THREADS>>>(x, alpha, delta, root, out);
}